// round 5
// baseline (speedup 1.0000x reference)
#include <cuda_runtime.h>
#include <math.h>

#define Nn 10000
#define Dn 15
#define Ln 16
#define Ee 320
#define OUTD 30
#define NH 5
#define HD 64

// ---------------- scratch (static device globals; no allocation) ----------------
__device__ float g_Mq_in[Ee*Ee], g_Mk_in[Ee*Ee], g_Mv_in[Ee*Ee];
__device__ float g_Mq_out[Ee*Ee], g_Mk_out[Ee*Ee], g_Mv_out[Ee*Ee];
__device__ float g_Qmat[Ee*Ee], g_Kmat_in[Ee*Ee], g_Kmat_out[Ee*Ee];
__device__ float g_Vmat_in[Ee*Ee], g_Vmat_out[Ee*Ee];
__device__ float g_qbias[Ee], g_kbias_in[Ee], g_kbias_out[Ee], g_vbias_in[Ee], g_vbias_out[Ee];
__device__ float g_Fmat[Ee*OUTD], g_fbias[OUTD];
__device__ int   g_rows_in[Nn*Ln], g_rows_out[Nn*Ln], g_rows_q0[Nn];
__device__ float g_Q[(size_t)Nn*Ln*Ee], g_K[(size_t)Nn*Ln*Ee], g_V[(size_t)Nn*Ln*Ee];
__device__ float g_Oin[(size_t)Nn*Ln*Ee], g_Oout[(size_t)Nn*Ln*Ee];
__device__ float g_Kf[(size_t)Nn*2*Ln*Ee], g_Vf[(size_t)Nn*2*Ln*Ee];
__device__ float g_q0[(size_t)Nn*Ee];

// ---------------- small precompute kernels ----------------

// out[k*E+j] = sum_t A[k*E+t] * Bw[j*E+t]      (A @ Bw.T)
__global__ void combine_abT(const float* __restrict__ A, const float* __restrict__ Bw,
                            float* __restrict__ out) {
    int idx = blockIdx.x * blockDim.x + threadIdx.x;
    if (idx >= Ee*Ee) return;
    int k = idx / Ee, j = idx % Ee;
    const float* ar = A + (size_t)k*Ee;
    const float* br = Bw + (size_t)j*Ee;
    float s = 0.f;
    #pragma unroll 8
    for (int t = 0; t < Ee; t++) s += ar[t] * br[t];
    out[idx] = s;
}

// out[k*E+j] = sum_e Awo[e*E+k] * Bq[j*E+e]    (Awo.T @ Bq.T)
__global__ void combine_aTbT(const float* __restrict__ Awo, const float* __restrict__ Bq,
                             float* __restrict__ out) {
    int idx = blockIdx.x * blockDim.x + threadIdx.x;
    if (idx >= Ee*Ee) return;
    int k = idx / Ee, j = idx % Ee;
    const float* br = Bq + (size_t)j*Ee;
    float s = 0.f;
    #pragma unroll 8
    for (int e = 0; e < Ee; e++) s += Awo[(size_t)e*Ee + k] * br[e];
    out[idx] = s;
}

// out[j] = sum_e bo[e]*Bq[j*E+e] + b2[j]
__global__ void combine_bias(const float* __restrict__ bo, const float* __restrict__ Bq,
                             const float* __restrict__ b2, float* __restrict__ out) {
    int j = blockIdx.x * blockDim.x + threadIdx.x;
    if (j >= Ee) return;
    const float* br = Bq + (size_t)j*Ee;
    float s = 0.f;
    #pragma unroll 8
    for (int e = 0; e < Ee; e++) s += bo[e] * br[e];
    out[j] = s + b2[j];
}

// Fmat[e*OUTD+j] = sum_t fow[t*E+e]*W[t*OUTD+j]
__global__ void combine_fmat(const float* __restrict__ fow, const float* __restrict__ W,
                             float* __restrict__ out) {
    int idx = blockIdx.x * blockDim.x + threadIdx.x;
    if (idx >= Ee*OUTD) return;
    int e = idx / OUTD, j = idx % OUTD;
    float s = 0.f;
    #pragma unroll 8
    for (int t = 0; t < Ee; t++) s += fow[(size_t)t*Ee + e] * W[(size_t)t*OUTD + j];
    out[idx] = s;
}

// fbias[j] = sum_t fob[t]*W[t*OUTD+j]
__global__ void combine_fbias(const float* __restrict__ fob, const float* __restrict__ W,
                              float* __restrict__ out) {
    int j = threadIdx.x;
    if (j >= OUTD) return;
    float s = 0.f;
    for (int t = 0; t < Ee; t++) s += fob[t] * W[(size_t)t*OUTD + j];
    out[j] = s;
}

__global__ void build_rows(const int* __restrict__ in_idx, const int* __restrict__ out_idx,
                           int* __restrict__ rin, int* __restrict__ rout, int* __restrict__ rq0) {
    int n = blockIdx.x * blockDim.x + threadIdx.x;
    if (n >= Nn) return;
    rin[n*Ln] = n;
    rout[n*Ln] = n;
    rq0[n] = n*Ln;
    #pragma unroll
    for (int d = 0; d < Dn; d++) {
        rin[n*Ln + 1 + d]  = in_idx[n*Dn + d];
        rout[n*Ln + 1 + d] = out_idx[n*Dn + d];
    }
}

// ---------------- fused multi-B GEMM ----------------
// One gathered A tile multiplied against NMAT weight matrices (shared A reuse).
// C_q[crow(m)] = gather(A)[m] @ B_q + bias_q, crow = (m/grp)*str + m%grp + off.
// Requires M % 64 == 0 (all call sites use M = 160000).
template<int NMAT>
__global__ void __launch_bounds__(256) gemm320_multi(
    const float* __restrict__ A, const int* __restrict__ rows,
    const float* __restrict__ B0, const float* __restrict__ B1, const float* __restrict__ B2,
    const float* __restrict__ bias0, const float* __restrict__ bias1, const float* __restrict__ bias2,
    float* __restrict__ C0, float* __restrict__ C1, float* __restrict__ C2,
    int out_grp, int out_str, int out_off)
{
    constexpr int BM = 64, BN = 64, BK = 16;
    __shared__ float As[BK][BM];
    __shared__ float Bs[NMAT][BK][BN];
    const int tid = threadIdx.x;
    const int bm = blockIdx.y * BM;
    const int bn = blockIdx.x * BN;
    const int tcol = tid & 15;   // 4 cols each
    const int trow = tid >> 4;   // 4 rows each

    const float* Bp[NMAT];
    const float* biasp[NMAT];
    float* Cp[NMAT];
    Bp[0] = B0; biasp[0] = bias0; Cp[0] = C0;
    if (NMAT > 1) { Bp[1] = B1; biasp[1] = bias1; Cp[1] = C1; }
    if (NMAT > 2) { Bp[2] = B2; biasp[2] = bias2; Cp[2] = C2; }

    float acc[NMAT][4][4];
    #pragma unroll
    for (int q = 0; q < NMAT; q++)
        #pragma unroll
        for (int i = 0; i < 4; i++)
            #pragma unroll
            for (int j = 0; j < 4; j++) acc[q][i][j] = 0.f;

    // A tile: 64 rows x 16 k, one float4 per thread
    const int aRow = tid >> 2;           // 0..63
    const int aCol = (tid & 3) << 2;     // 0,4,8,12
    const size_t ga = (size_t)(rows ? rows[bm + aRow] : bm + aRow) * Ee;

    // B tiles: 16 rows x 64 cols each, one float4 per thread per matrix
    const int bRow = tid >> 4;           // 0..15
    const int bCol = (tid & 15) << 2;    // 0..60

    for (int k0 = 0; k0 < Ee; k0 += BK) {
        float4 a4 = *(const float4*)(A + ga + k0 + aCol);
        float4 b4[NMAT];
        #pragma unroll
        for (int q = 0; q < NMAT; q++)
            b4[q] = *(const float4*)(Bp[q] + (size_t)(k0 + bRow)*Ee + bn + bCol);

        As[aCol+0][aRow] = a4.x; As[aCol+1][aRow] = a4.y;
        As[aCol+2][aRow] = a4.z; As[aCol+3][aRow] = a4.w;
        #pragma unroll
        for (int q = 0; q < NMAT; q++)
            *(float4*)&Bs[q][bRow][bCol] = b4[q];
        __syncthreads();

        #pragma unroll
        for (int kk = 0; kk < BK; kk++) {
            float ar[4];
            #pragma unroll
            for (int i = 0; i < 4; i++) ar[i] = As[kk][trow*4 + i];
            #pragma unroll
            for (int q = 0; q < NMAT; q++) {
                float br[4];
                #pragma unroll
                for (int j = 0; j < 4; j++) br[j] = Bs[q][kk][tcol*4 + j];
                #pragma unroll
                for (int i = 0; i < 4; i++)
                    #pragma unroll
                    for (int j = 0; j < 4; j++)
                        acc[q][i][j] += ar[i] * br[j];
            }
        }
        __syncthreads();
    }

    #pragma unroll
    for (int q = 0; q < NMAT; q++) {
        float bb[4];
        #pragma unroll
        for (int j = 0; j < 4; j++) bb[j] = biasp[q][bn + tcol*4 + j];
        #pragma unroll
        for (int i = 0; i < 4; i++) {
            int m = bm + trow*4 + i;
            int crow = (m / out_grp) * out_str + (m % out_grp) + out_off;
            float4 o;
            o.x = acc[q][i][0] + bb[0];
            o.y = acc[q][i][1] + bb[1];
            o.z = acc[q][i][2] + bb[2];
            o.w = acc[q][i][3] + bb[3];
            *(float4*)(Cp[q] + (size_t)crow*Ee + bn + tcol*4) = o;
        }
    }
}

// ---------------- single-B GEMM with M guard (used for q0: M = 10000) ----------------
__global__ void __launch_bounds__(256) gemm320(
    const float* __restrict__ A, const int* __restrict__ rows, int M,
    const float* __restrict__ B, const float* __restrict__ bias,
    float* __restrict__ C)
{
    constexpr int BM = 64, BN = 64, BK = 16;
    __shared__ float As[BK][BM];
    __shared__ float Bs[BK][BN];
    const int tid = threadIdx.x;
    const int bm = blockIdx.y * BM;
    const int bn = blockIdx.x * BN;
    const int tcol = tid & 15;
    const int trow = tid >> 4;

    float acc[4][4];
    #pragma unroll
    for (int i = 0; i < 4; i++)
        #pragma unroll
        for (int j = 0; j < 4; j++) acc[i][j] = 0.f;

    const int aRow = tid >> 2;
    const int aCol = (tid & 3) << 2;
    int r = bm + aRow; if (r >= M) r = M - 1;
    const size_t ga = (size_t)(rows ? rows[r] : r) * Ee;
    const int bRow = tid >> 4;
    const int bCol = (tid & 15) << 2;

    for (int k0 = 0; k0 < Ee; k0 += BK) {
        float4 a4 = *(const float4*)(A + ga + k0 + aCol);
        float4 b4 = *(const float4*)(B + (size_t)(k0 + bRow)*Ee + bn + bCol);
        As[aCol+0][aRow] = a4.x; As[aCol+1][aRow] = a4.y;
        As[aCol+2][aRow] = a4.z; As[aCol+3][aRow] = a4.w;
        *(float4*)&Bs[bRow][bCol] = b4;
        __syncthreads();

        #pragma unroll
        for (int kk = 0; kk < BK; kk++) {
            float ar[4], br[4];
            #pragma unroll
            for (int i = 0; i < 4; i++) ar[i] = As[kk][trow*4 + i];
            #pragma unroll
            for (int j = 0; j < 4; j++) br[j] = Bs[kk][tcol*4 + j];
            #pragma unroll
            for (int i = 0; i < 4; i++)
                #pragma unroll
                for (int j = 0; j < 4; j++)
                    acc[i][j] += ar[i] * br[j];
        }
        __syncthreads();
    }

    float bb[4];
    #pragma unroll
    for (int j = 0; j < 4; j++) bb[j] = bias[bn + tcol*4 + j];
    #pragma unroll
    for (int i = 0; i < 4; i++) {
        int m = bm + trow*4 + i;
        if (m < M) {
            float4 o;
            o.x = acc[i][0] + bb[0];
            o.y = acc[i][1] + bb[1];
            o.z = acc[i][2] + bb[2];
            o.w = acc[i][3] + bb[3];
            *(float4*)(C + (size_t)m*Ee + bn + tcol*4) = o;
        }
    }
}

// ---------------- per-node 5-head L=16 attention (writes pre-output-proj O) ----------------
__global__ void __launch_bounds__(256) attn16(
    const float* __restrict__ Q, const float* __restrict__ K,
    const float* __restrict__ V, float* __restrict__ O)
{
    constexpr int LP = 68;
    __shared__ float sq[Ln][LP], sk[Ln][LP], sv[Ln][LP];
    __shared__ float ss[Ln][Ln + 1];
    const int n = blockIdx.x;
    const int tid = threadIdx.x;
    const size_t base = (size_t)n * Ln * Ee;

    const int ll = tid >> 4;          // 0..15
    const int lc = (tid & 15) << 2;   // 0..60

    for (int h = 0; h < NH; h++) {
        const int hc = h * HD;
        float4 q4 = *(const float4*)(Q + base + (size_t)ll*Ee + hc + lc);
        float4 k4 = *(const float4*)(K + base + (size_t)ll*Ee + hc + lc);
        float4 v4 = *(const float4*)(V + base + (size_t)ll*Ee + hc + lc);
        sq[ll][lc+0]=q4.x; sq[ll][lc+1]=q4.y; sq[ll][lc+2]=q4.z; sq[ll][lc+3]=q4.w;
        sk[ll][lc+0]=k4.x; sk[ll][lc+1]=k4.y; sk[ll][lc+2]=k4.z; sk[ll][lc+3]=k4.w;
        sv[ll][lc+0]=v4.x; sv[ll][lc+1]=v4.y; sv[ll][lc+2]=v4.z; sv[ll][lc+3]=v4.w;
        __syncthreads();

        {
            const int sl = tid >> 4, sm = tid & 15;
            float s = 0.f;
            #pragma unroll
            for (int c = 0; c < HD; c++) s += sq[sl][c] * sk[sm][c];
            ss[sl][sm] = s * 0.125f;  // 1/sqrt(64)
        }
        __syncthreads();

        if (tid < Ln) {
            float mx = -1e30f;
            #pragma unroll
            for (int m = 0; m < Ln; m++) mx = fmaxf(mx, ss[tid][m]);
            float sum = 0.f;
            #pragma unroll
            for (int m = 0; m < Ln; m++) { float e = expf(ss[tid][m] - mx); ss[tid][m] = e; sum += e; }
            float inv = 1.f / sum;
            #pragma unroll
            for (int m = 0; m < Ln; m++) ss[tid][m] *= inv;
        }
        __syncthreads();

        #pragma unroll
        for (int i = 0; i < 4; i++) {
            int idx = tid + i * 256;
            int ol = idx >> 6, oc = idx & 63;
            float a = 0.f;
            #pragma unroll
            for (int m = 0; m < Ln; m++) a += ss[ol][m] * sv[m][oc];
            O[base + (size_t)ol*Ee + hc + oc] = a;
        }
        __syncthreads();
    }
}

// ---------------- final 1-head attention over 32 tokens + fused output proj + ELU ----------------
__global__ void __launch_bounds__(256) final_attn(
    const float* __restrict__ q0, const float* __restrict__ Kf,
    const float* __restrict__ Vf, const float* __restrict__ Fmat,
    const float* __restrict__ fbias, float* __restrict__ out)
{
    __shared__ float sqv[Ee];
    __shared__ float sc[32];
    __shared__ float so[Ee];
    const int n = blockIdx.x;
    const int tid = threadIdx.x;
    const int warp = tid >> 5, lane = tid & 31;
    const float scale = 0.05590169943749474f;  // 1/sqrt(320)

    for (int e = tid; e < Ee; e += 256) sqv[e] = q0[(size_t)n*Ee + e];
    __syncthreads();

    #pragma unroll
    for (int i = 0; i < 4; i++) {
        int m = warp*4 + i;
        const float* kr = Kf + ((size_t)n*32 + m) * Ee;
        float s = 0.f;
        for (int e = lane; e < Ee; e += 32) s += sqv[e] * kr[e];
        #pragma unroll
        for (int o = 16; o > 0; o >>= 1) s += __shfl_down_sync(0xffffffffu, s, o);
        if (lane == 0) sc[m] = s * scale;
    }
    __syncthreads();

    if (warp == 0) {
        float v = sc[lane];
        float mx = v;
        #pragma unroll
        for (int o = 16; o > 0; o >>= 1) mx = fmaxf(mx, __shfl_xor_sync(0xffffffffu, mx, o));
        float ex = expf(v - mx);
        float sm = ex;
        #pragma unroll
        for (int o = 16; o > 0; o >>= 1) sm += __shfl_xor_sync(0xffffffffu, sm, o);
        sc[lane] = ex / sm;
    }
    __syncthreads();

    for (int e = tid; e < Ee; e += 256) {
        const float* vr = Vf + (size_t)n*32*Ee + e;
        float a = 0.f;
        #pragma unroll
        for (int m = 0; m < 32; m++) a += sc[m] * vr[(size_t)m*Ee];
        so[e] = a;
    }
    __syncthreads();

    #pragma unroll
    for (int i = 0; i < 4; i++) {
        int j = warp*4 + i;
        if (j < OUTD) {
            float s = 0.f;
            for (int e = lane; e < Ee; e += 32) s += so[e] * Fmat[(size_t)e*OUTD + j];
            #pragma unroll
            for (int o = 16; o > 0; o >>= 1) s += __shfl_down_sync(0xffffffffu, s, o);
            if (lane == 0) {
                float x = s + fbias[j];
                out[(size_t)n*OUTD + j] = x > 0.f ? x : expm1f(x);
            }
        }
    }
}

// ---------------- host ----------------
#define GETSYM(p, s) do { void* _t; cudaGetSymbolAddress(&_t, s); p = decltype(p)(_t); } while (0)

extern "C" void kernel_launch(void* const* d_in, const int* in_sizes, int n_in,
                              void* d_out, int out_size)
{
    const float* X        = (const float*)d_in[0];
    const int*   in_idx   = (const int*)  d_in[1];
    const int*   out_idx  = (const int*)  d_in[2];
    const float* in_Wq    = (const float*)d_in[3];
    const float* in_Wk    = (const float*)d_in[4];
    const float* in_Wv    = (const float*)d_in[5];
    const float* in_qkv_w = (const float*)d_in[6];
    const float* in_qkv_b = (const float*)d_in[7];
    const float* in_o_w   = (const float*)d_in[8];
    const float* in_o_b   = (const float*)d_in[9];
    const float* out_Wq   = (const float*)d_in[10];
    const float* out_Wk   = (const float*)d_in[11];
    const float* out_Wv   = (const float*)d_in[12];
    const float* out_qkv_w= (const float*)d_in[13];
    const float* out_qkv_b= (const float*)d_in[14];
    const float* out_o_w  = (const float*)d_in[15];
    const float* out_o_b  = (const float*)d_in[16];
    const float* fin_qkv_w= (const float*)d_in[17];
    const float* fin_qkv_b= (const float*)d_in[18];
    const float* fin_o_w  = (const float*)d_in[19];
    const float* fin_o_b  = (const float*)d_in[20];
    const float* Wfin     = (const float*)d_in[21];
    float* out = (float*)d_out;

    float *Mq_in, *Mk_in, *Mv_in, *Mq_out, *Mk_out, *Mv_out;
    float *Qmat, *Kmat_in, *Kmat_out, *Vmat_in, *Vmat_out;
    float *qbias, *kbias_in, *kbias_out, *vbias_in, *vbias_out;
    float *Fmat, *fbias, *Q, *K, *V, *Oin, *Oout, *Kf, *Vf, *q0;
    int *rows_in, *rows_out, *rows_q0;
    GETSYM(Mq_in, g_Mq_in);   GETSYM(Mk_in, g_Mk_in);   GETSYM(Mv_in, g_Mv_in);
    GETSYM(Mq_out, g_Mq_out); GETSYM(Mk_out, g_Mk_out); GETSYM(Mv_out, g_Mv_out);
    GETSYM(Qmat, g_Qmat);     GETSYM(Kmat_in, g_Kmat_in); GETSYM(Kmat_out, g_Kmat_out);
    GETSYM(Vmat_in, g_Vmat_in); GETSYM(Vmat_out, g_Vmat_out);
    GETSYM(qbias, g_qbias);   GETSYM(kbias_in, g_kbias_in); GETSYM(kbias_out, g_kbias_out);
    GETSYM(vbias_in, g_vbias_in); GETSYM(vbias_out, g_vbias_out);
    GETSYM(Fmat, g_Fmat);     GETSYM(fbias, g_fbias);
    GETSYM(Q, g_Q); GETSYM(K, g_K); GETSYM(V, g_V);
    GETSYM(Oin, g_Oin); GETSYM(Oout, g_Oout);
    GETSYM(Kf, g_Kf); GETSYM(Vf, g_Vf); GETSYM(q0, g_q0);
    GETSYM(rows_in, g_rows_in); GETSYM(rows_out, g_rows_out); GETSYM(rows_q0, g_rows_q0);

    const int CB = 256;
    const int nEE = (Ee*Ee + CB - 1) / CB;

    // 1) row gather tables
    build_rows<<<(Nn + CB - 1)/CB, CB>>>(in_idx, out_idx, rows_in, rows_out, rows_q0);

    // 2) combined projection matrices: Mx = Wx @ wx.T  (wx = qkv_w slice)
    combine_abT<<<nEE, CB>>>(in_Wq,  in_qkv_w,             Mq_in);
    combine_abT<<<nEE, CB>>>(in_Wk,  in_qkv_w + Ee*Ee,     Mk_in);
    combine_abT<<<nEE, CB>>>(in_Wv,  in_qkv_w + 2*Ee*Ee,   Mv_in);
    combine_abT<<<nEE, CB>>>(out_Wq, out_qkv_w,            Mq_out);
    combine_abT<<<nEE, CB>>>(out_Wk, out_qkv_w + Ee*Ee,    Mk_out);
    combine_abT<<<nEE, CB>>>(out_Wv, out_qkv_w + 2*Ee*Ee,  Mv_out);

    // 3) fold layer output-proj into final q/k/v projections: Xmat = wo.T @ wxf.T
    combine_aTbT<<<nEE, CB>>>(in_o_w,  fin_qkv_w,            Qmat);
    combine_aTbT<<<nEE, CB>>>(in_o_w,  fin_qkv_w + Ee*Ee,    Kmat_in);
    combine_aTbT<<<nEE, CB>>>(out_o_w, fin_qkv_w + Ee*Ee,    Kmat_out);
    combine_aTbT<<<nEE, CB>>>(in_o_w,  fin_qkv_w + 2*Ee*Ee,  Vmat_in);
    combine_aTbT<<<nEE, CB>>>(out_o_w, fin_qkv_w + 2*Ee*Ee,  Vmat_out);
    combine_bias<<<2, 160>>>(in_o_b,  fin_qkv_w,           fin_qkv_b,          qbias);
    combine_bias<<<2, 160>>>(in_o_b,  fin_qkv_w + Ee*Ee,   fin_qkv_b + Ee,     kbias_in);
    combine_bias<<<2, 160>>>(out_o_b, fin_qkv_w + Ee*Ee,   fin_qkv_b + Ee,     kbias_out);
    combine_bias<<<2, 160>>>(in_o_b,  fin_qkv_w + 2*Ee*Ee, fin_qkv_b + 2*Ee,   vbias_in);
    combine_bias<<<2, 160>>>(out_o_b, fin_qkv_w + 2*Ee*Ee, fin_qkv_b + 2*Ee,   vbias_out);

    // 4) fold final output-proj into readout: Fmat = wof.T @ W
    combine_fmat<<<(Ee*OUTD + CB - 1)/CB, CB>>>(fin_o_w, Wfin, Fmat);
    combine_fbias<<<1, 32>>>(fin_o_b, Wfin, fbias);

    const int Mfull = Nn * Ln;           // 160000, divisible by 64
    dim3 gemmGrid(Ee/64, Mfull/64);
    dim3 gemmGridQ0(Ee/64, (Nn + 63)/64);

    // 5) in-layer fused Q/K/V (one gathered-A pass), attention -> Oin
    gemm320_multi<3><<<gemmGrid, 256>>>(X, rows_in,
        Mq_in, Mk_in, Mv_in,
        in_qkv_b, in_qkv_b + Ee, in_qkv_b + 2*Ee,
        Q, K, V, 16, 16, 0);
    attn16<<<Nn, 256>>>(Q, K, V, Oin);

    // 6) out-layer
    gemm320_multi<3><<<gemmGrid, 256>>>(X, rows_out,
        Mq_out, Mk_out, Mv_out,
        out_qkv_b, out_qkv_b + Ee, out_qkv_b + 2*Ee,
        Q, K, V, 16, 16, 0);
    attn16<<<Nn, 256>>>(Q, K, V, Oout);

    // 7) final-layer K/V fused per source (interleaved halves: rows n*32+l, n*32+16+l)
    gemm320_multi<2><<<gemmGrid, 256>>>(Oin, nullptr,
        Kmat_in, Vmat_in, nullptr,
        kbias_in, vbias_in, nullptr,
        Kf, Vf, nullptr, 16, 32, 0);
    gemm320_multi<2><<<gemmGrid, 256>>>(Oout, nullptr,
        Kmat_out, Vmat_out, nullptr,
        kbias_out, vbias_out, nullptr,
        Kf, Vf, nullptr, 16, 32, 16);
    gemm320<<<gemmGridQ0, 256>>>(Oin, rows_q0, Nn, Qmat, qbias, q0);

    // 8) final attention + fused readout + ELU
    final_attn<<<Nn, 256>>>(q0, Kf, Vf, Fmat, fbias, out);
}

// round 6
// speedup vs baseline: 2.7125x; 2.7125x over previous
#include <cuda_runtime.h>
#include <math.h>
#include <stdint.h>

#define Nn 10000
#define Dn 15
#define Ln 16
#define Ee 320
#define OUTD 30
#define NH 5
#define HD 64

// ---------------- scratch (static device globals; no allocation) ----------------
__device__ float g_Mq_in[Ee*Ee], g_Mk_in[Ee*Ee], g_Mv_in[Ee*Ee];
__device__ float g_Mq_out[Ee*Ee], g_Mk_out[Ee*Ee], g_Mv_out[Ee*Ee];
__device__ float g_Qmat[Ee*Ee], g_Kmat_in[Ee*Ee], g_Kmat_out[Ee*Ee];
__device__ float g_Vmat_in[Ee*Ee], g_Vmat_out[Ee*Ee];
__device__ float g_T_in_o[Ee*Ee], g_T_out_o[Ee*Ee], g_T_fin_o[Ee*Ee];
__device__ float g_qbias[Ee], g_kbias_in[Ee], g_kbias_out[Ee], g_vbias_in[Ee], g_vbias_out[Ee];
__device__ float g_Fmat[Ee*OUTD], g_fbias[OUTD];
__device__ int   g_rows_in[Nn*Ln], g_rows_out[Nn*Ln], g_rows_q0[Nn];
__device__ float g_Q[(size_t)Nn*Ln*Ee], g_K[(size_t)Nn*Ln*Ee], g_V[(size_t)Nn*Ln*Ee];
__device__ float g_Oin[(size_t)Nn*Ln*Ee], g_Oout[(size_t)Nn*Ln*Ee];
__device__ float g_Kf[(size_t)Nn*2*Ln*Ee], g_Vf[(size_t)Nn*2*Ln*Ee];
__device__ float g_q0[(size_t)Nn*Ee];

// ---------------- helpers ----------------
__device__ __forceinline__ float f2tf32(float x) {
    uint32_t u;
    asm("cvt.rna.tf32.f32 %0, %1;" : "=r"(u) : "f"(x));
    return __uint_as_float(u);
}

__device__ __forceinline__ void mma_tf32(float* d, const uint32_t* a, uint32_t b0, uint32_t b1) {
    asm volatile(
        "mma.sync.aligned.m16n8k8.row.col.f32.tf32.tf32.f32 "
        "{%0,%1,%2,%3}, {%4,%5,%6,%7}, {%8,%9}, {%0,%1,%2,%3};"
        : "+f"(d[0]), "+f"(d[1]), "+f"(d[2]), "+f"(d[3])
        : "r"(a[0]), "r"(a[1]), "r"(a[2]), "r"(a[3]), "r"(b0), "r"(b1));
}

// ---------------- precompute kernels ----------------

// 320x320 transpose via smem tiles
__global__ void transpose320(const float* __restrict__ in, float* __restrict__ out) {
    __shared__ float tile[32][33];
    int bx = blockIdx.x * 32, by = blockIdx.y * 32;
    int x = bx + threadIdx.x;
    #pragma unroll
    for (int i = 0; i < 32; i += 8) {
        int y = by + threadIdx.y + i;
        tile[threadIdx.y + i][threadIdx.x] = in[(size_t)y*Ee + x];
    }
    __syncthreads();
    x = by + threadIdx.x;
    #pragma unroll
    for (int i = 0; i < 32; i += 8) {
        int y = bx + threadIdx.y + i;
        out[(size_t)y*Ee + x] = tile[threadIdx.x][threadIdx.y + i];
    }
}

// warp-per-output: out[k*E+j] = sum_t A[k*E+t] * Bw[j*E+t]   (A @ Bw.T), coalesced
__global__ void combine_abT_w(const float* __restrict__ A, const float* __restrict__ Bw,
                              float* __restrict__ out) {
    int gw = (blockIdx.x * 256 + threadIdx.x) >> 5;
    int lane = threadIdx.x & 31;
    #pragma unroll
    for (int r = 0; r < 4; r++) {
        int o = gw * 4 + r;
        if (o >= Ee*Ee) return;
        int k = o / Ee, j = o % Ee;
        const float* ar = A + (size_t)k*Ee;
        const float* br = Bw + (size_t)j*Ee;
        float s = 0.f;
        #pragma unroll
        for (int t = lane, i = 0; i < Ee/32; t += 32, i++) s += ar[t] * br[t];
        #pragma unroll
        for (int off = 16; off > 0; off >>= 1) s += __shfl_down_sync(0xffffffffu, s, off);
        if (lane == 0) out[o] = s;
    }
}

// warp-per-output: out[j] = sum_e bo[e]*Bq[j*E+e] + b2[j]
__global__ void combine_bias_w(const float* __restrict__ bo, const float* __restrict__ Bq,
                               const float* __restrict__ b2, float* __restrict__ out) {
    int j = (blockIdx.x * 256 + threadIdx.x) >> 5;
    int lane = threadIdx.x & 31;
    if (j >= Ee) return;
    const float* br = Bq + (size_t)j*Ee;
    float s = 0.f;
    #pragma unroll
    for (int e = lane, i = 0; i < Ee/32; e += 32, i++) s += bo[e] * br[e];
    #pragma unroll
    for (int off = 16; off > 0; off >>= 1) s += __shfl_down_sync(0xffffffffu, s, off);
    if (lane == 0) out[j] = s + b2[j];
}

// warp-per-output: Fmat[e*OUTD+j] = sum_t fowT[e*E+t]*W[t*OUTD+j]
__global__ void combine_fmat_w(const float* __restrict__ fowT, const float* __restrict__ W,
                               float* __restrict__ out) {
    int o = (blockIdx.x * 256 + threadIdx.x) >> 5;
    int lane = threadIdx.x & 31;
    if (o >= Ee*OUTD) return;
    int e = o / OUTD, j = o % OUTD;
    const float* fr = fowT + (size_t)e*Ee;
    float s = 0.f;
    #pragma unroll
    for (int t = lane, i = 0; i < Ee/32; t += 32, i++) s += fr[t] * W[(size_t)t*OUTD + j];
    #pragma unroll
    for (int off = 16; off > 0; off >>= 1) s += __shfl_down_sync(0xffffffffu, s, off);
    if (lane == 0) out[o] = s;
}

// fbias[j] = sum_t fob[t]*W[t*OUTD+j]
__global__ void combine_fbias_w(const float* __restrict__ fob, const float* __restrict__ W,
                                float* __restrict__ out) {
    int warp = threadIdx.x >> 5, lane = threadIdx.x & 31;
    for (int j = warp; j < OUTD; j += 8) {
        float s = 0.f;
        #pragma unroll
        for (int t = lane, i = 0; i < Ee/32; t += 32, i++) s += fob[t] * W[(size_t)t*OUTD + j];
        #pragma unroll
        for (int off = 16; off > 0; off >>= 1) s += __shfl_down_sync(0xffffffffu, s, off);
        if (lane == 0) out[j] = s;
    }
}

__global__ void build_rows(const int* __restrict__ in_idx, const int* __restrict__ out_idx,
                           int* __restrict__ rin, int* __restrict__ rout, int* __restrict__ rq0) {
    int n = blockIdx.x * blockDim.x + threadIdx.x;
    if (n >= Nn) return;
    rin[n*Ln] = n;
    rout[n*Ln] = n;
    rq0[n] = n*Ln;
    #pragma unroll
    for (int d = 0; d < Dn; d++) {
        rin[n*Ln + 1 + d]  = in_idx[n*Dn + d];
        rout[n*Ln + 1 + d] = out_idx[n*Dn + d];
    }
}

// ---------------- tensor-core multi-B GEMM (tf32 HMMA, fp32 accumulate) ----------------
// C_q[crow(m)] = gather(A)[m] @ B_q + bias_q, crow = (m/grp)*str + (m%grp) + off.
// BM=128, BN=64, BK=32. 8 warps; warp tile 32x32 via m16n8k8. Requires M % 128 == 0.
template<int NMAT>
__global__ void __launch_bounds__(256) gemm_tc(
    const float* __restrict__ A, const int* __restrict__ rows,
    const float* __restrict__ B0, const float* __restrict__ B1, const float* __restrict__ B2,
    const float* __restrict__ bias0, const float* __restrict__ bias1, const float* __restrict__ bias2,
    float* __restrict__ C0, float* __restrict__ C1, float* __restrict__ C2,
    int out_grp, int out_str, int out_off)
{
    constexpr int BM = 128, BN = 64, BK = 32;
    constexpr int ASTR = 36;   // bank-conflict-free A frag loads (4g+t)
    constexpr int BSTR = 72;   // bank-conflict-free B frag loads (8t+g)
    __shared__ float As[BM * ASTR];
    __shared__ float Bs[NMAT][BK * BSTR];

    const int tid = threadIdx.x;
    const int bm = blockIdx.y * BM;
    const int bn = blockIdx.x * BN;
    const int warpId = tid >> 5, lane = tid & 31;
    const int wm = (warpId & 3) * 32;
    const int wn = (warpId >> 2) * 32;
    const int g = lane >> 2, t = lane & 3;

    const float* Bp[NMAT]; const float* biasp[NMAT]; float* Cp[NMAT];
    Bp[0] = B0; biasp[0] = bias0; Cp[0] = C0;
    if (NMAT > 1) { Bp[1] = B1; biasp[1] = bias1; Cp[1] = C1; }
    if (NMAT > 2) { Bp[2] = B2; biasp[2] = bias2; Cp[2] = C2; }

    float acc[NMAT][2][4][4];
    #pragma unroll
    for (int q = 0; q < NMAT; q++)
        #pragma unroll
        for (int mi = 0; mi < 2; mi++)
            #pragma unroll
            for (int ni = 0; ni < 4; ni++)
                #pragma unroll
                for (int v = 0; v < 4; v++) acc[q][mi][ni][v] = 0.f;

    // A loader: 4 rows/thread (rows aRow + 32i), 4 cols each
    const int aRow = tid >> 3;
    const int aCol = (tid & 7) * 4;
    size_t gA[4];
    #pragma unroll
    for (int i = 0; i < 4; i++) {
        int m = bm + aRow + i*32;
        gA[i] = (size_t)(rows ? rows[m] : m) * Ee;
    }
    // B loader: 2 rows/thread/matrix
    const int bRow = tid >> 4;
    const int bCol = (tid & 15) * 4;

    for (int k0 = 0; k0 < Ee; k0 += BK) {
        __syncthreads();
        #pragma unroll
        for (int i = 0; i < 4; i++) {
            float4 a = *(const float4*)(A + gA[i] + k0 + aCol);
            float4 c;
            c.x = f2tf32(a.x); c.y = f2tf32(a.y); c.z = f2tf32(a.z); c.w = f2tf32(a.w);
            *(float4*)&As[(aRow + i*32)*ASTR + aCol] = c;
        }
        #pragma unroll
        for (int q = 0; q < NMAT; q++) {
            #pragma unroll
            for (int i = 0; i < 2; i++) {
                int kr = bRow + i*16;
                float4 b = *(const float4*)(Bp[q] + (size_t)(k0 + kr)*Ee + bn + bCol);
                float4 c;
                c.x = f2tf32(b.x); c.y = f2tf32(b.y); c.z = f2tf32(b.z); c.w = f2tf32(b.w);
                *(float4*)&Bs[q][kr*BSTR + bCol] = c;
            }
        }
        __syncthreads();

        #pragma unroll
        for (int kk = 0; kk < BK; kk += 8) {
            uint32_t afr[2][4];
            #pragma unroll
            for (int mi = 0; mi < 2; mi++) {
                int r0 = wm + mi*16 + g;
                afr[mi][0] = __float_as_uint(As[(r0    )*ASTR + kk + t    ]);
                afr[mi][1] = __float_as_uint(As[(r0 + 8)*ASTR + kk + t    ]);
                afr[mi][2] = __float_as_uint(As[(r0    )*ASTR + kk + t + 4]);
                afr[mi][3] = __float_as_uint(As[(r0 + 8)*ASTR + kk + t + 4]);
            }
            #pragma unroll
            for (int q = 0; q < NMAT; q++) {
                #pragma unroll
                for (int ni = 0; ni < 4; ni++) {
                    int nc = wn + ni*8 + g;
                    uint32_t b0 = __float_as_uint(Bs[q][(kk + t    )*BSTR + nc]);
                    uint32_t b1 = __float_as_uint(Bs[q][(kk + t + 4)*BSTR + nc]);
                    #pragma unroll
                    for (int mi = 0; mi < 2; mi++)
                        mma_tf32(acc[q][mi][ni], afr[mi], b0, b1);
                }
            }
        }
    }

    // epilogue: c0,c1 = (row g, cols 2t,2t+1); c2,c3 = (row g+8, same cols)
    #pragma unroll
    for (int q = 0; q < NMAT; q++) {
        #pragma unroll
        for (int ni = 0; ni < 4; ni++) {
            int n = bn + wn + ni*8 + 2*t;
            float bb0 = biasp[q][n], bb1 = biasp[q][n+1];
            #pragma unroll
            for (int mi = 0; mi < 2; mi++) {
                int m0 = bm + wm + mi*16 + g;
                int m1 = m0 + 8;
                int cr0 = (m0 / out_grp) * out_str + (m0 % out_grp) + out_off;
                int cr1 = (m1 / out_grp) * out_str + (m1 % out_grp) + out_off;
                float2 v0, v1;
                v0.x = acc[q][mi][ni][0] + bb0; v0.y = acc[q][mi][ni][1] + bb1;
                v1.x = acc[q][mi][ni][2] + bb0; v1.y = acc[q][mi][ni][3] + bb1;
                *(float2*)(Cp[q] + (size_t)cr0*Ee + n) = v0;
                *(float2*)(Cp[q] + (size_t)cr1*Ee + n) = v1;
            }
        }
    }
}

// ---------------- single-B SIMT GEMM with M guard (q0: M = 10000, fp32 exact) ----------------
__global__ void __launch_bounds__(256) gemm320(
    const float* __restrict__ A, const int* __restrict__ rows, int M,
    const float* __restrict__ B, const float* __restrict__ bias,
    float* __restrict__ C)
{
    constexpr int BM = 64, BN = 64, BK = 16;
    __shared__ float As[BK][BM];
    __shared__ float Bs[BK][BN];
    const int tid = threadIdx.x;
    const int bm = blockIdx.y * BM;
    const int bn = blockIdx.x * BN;
    const int tcol = tid & 15;
    const int trow = tid >> 4;

    float acc[4][4];
    #pragma unroll
    for (int i = 0; i < 4; i++)
        #pragma unroll
        for (int j = 0; j < 4; j++) acc[i][j] = 0.f;

    const int aRow = tid >> 2;
    const int aCol = (tid & 3) << 2;
    int r = bm + aRow; if (r >= M) r = M - 1;
    const size_t ga = (size_t)(rows ? rows[r] : r) * Ee;
    const int bRow = tid >> 4;
    const int bCol = (tid & 15) << 2;

    for (int k0 = 0; k0 < Ee; k0 += BK) {
        float4 a4 = *(const float4*)(A + ga + k0 + aCol);
        float4 b4 = *(const float4*)(B + (size_t)(k0 + bRow)*Ee + bn + bCol);
        As[aCol+0][aRow] = a4.x; As[aCol+1][aRow] = a4.y;
        As[aCol+2][aRow] = a4.z; As[aCol+3][aRow] = a4.w;
        *(float4*)&Bs[bRow][bCol] = b4;
        __syncthreads();

        #pragma unroll
        for (int kk = 0; kk < BK; kk++) {
            float ar[4], br[4];
            #pragma unroll
            for (int i = 0; i < 4; i++) ar[i] = As[kk][trow*4 + i];
            #pragma unroll
            for (int j = 0; j < 4; j++) br[j] = Bs[kk][tcol*4 + j];
            #pragma unroll
            for (int i = 0; i < 4; i++)
                #pragma unroll
                for (int j = 0; j < 4; j++)
                    acc[i][j] += ar[i] * br[j];
        }
        __syncthreads();
    }

    float bb[4];
    #pragma unroll
    for (int j = 0; j < 4; j++) bb[j] = bias[bn + tcol*4 + j];
    #pragma unroll
    for (int i = 0; i < 4; i++) {
        int m = bm + trow*4 + i;
        if (m < M) {
            float4 o;
            o.x = acc[i][0] + bb[0];
            o.y = acc[i][1] + bb[1];
            o.z = acc[i][2] + bb[2];
            o.w = acc[i][3] + bb[3];
            *(float4*)(C + (size_t)m*Ee + bn + tcol*4) = o;
        }
    }
}

// ---------------- per-node 5-head L=16 attention (writes pre-output-proj O) ----------------
__global__ void __launch_bounds__(256) attn16(
    const float* __restrict__ Q, const float* __restrict__ K,
    const float* __restrict__ V, float* __restrict__ O)
{
    constexpr int LP = 68;
    __shared__ float sq[Ln][LP], sk[Ln][LP], sv[Ln][LP];
    __shared__ float ss[Ln][Ln + 1];
    const int n = blockIdx.x;
    const int tid = threadIdx.x;
    const size_t base = (size_t)n * Ln * Ee;

    const int ll = tid >> 4;          // 0..15
    const int lc = (tid & 15) << 2;   // 0..60

    for (int h = 0; h < NH; h++) {
        const int hc = h * HD;
        float4 q4 = *(const float4*)(Q + base + (size_t)ll*Ee + hc + lc);
        float4 k4 = *(const float4*)(K + base + (size_t)ll*Ee + hc + lc);
        float4 v4 = *(const float4*)(V + base + (size_t)ll*Ee + hc + lc);
        sq[ll][lc+0]=q4.x; sq[ll][lc+1]=q4.y; sq[ll][lc+2]=q4.z; sq[ll][lc+3]=q4.w;
        sk[ll][lc+0]=k4.x; sk[ll][lc+1]=k4.y; sk[ll][lc+2]=k4.z; sk[ll][lc+3]=k4.w;
        sv[ll][lc+0]=v4.x; sv[ll][lc+1]=v4.y; sv[ll][lc+2]=v4.z; sv[ll][lc+3]=v4.w;
        __syncthreads();

        {
            const int sl = tid >> 4, sm = tid & 15;
            float s = 0.f;
            #pragma unroll
            for (int c = 0; c < HD; c++) s += sq[sl][c] * sk[sm][c];
            ss[sl][sm] = s * 0.125f;  // 1/sqrt(64)
        }
        __syncthreads();

        if (tid < Ln) {
            float mx = -1e30f;
            #pragma unroll
            for (int m = 0; m < Ln; m++) mx = fmaxf(mx, ss[tid][m]);
            float sum = 0.f;
            #pragma unroll
            for (int m = 0; m < Ln; m++) { float e = expf(ss[tid][m] - mx); ss[tid][m] = e; sum += e; }
            float inv = 1.f / sum;
            #pragma unroll
            for (int m = 0; m < Ln; m++) ss[tid][m] *= inv;
        }
        __syncthreads();

        #pragma unroll
        for (int i = 0; i < 4; i++) {
            int idx = tid + i * 256;
            int ol = idx >> 6, oc = idx & 63;
            float a = 0.f;
            #pragma unroll
            for (int m = 0; m < Ln; m++) a += ss[ol][m] * sv[m][oc];
            O[base + (size_t)ol*Ee + hc + oc] = a;
        }
        __syncthreads();
    }
}

// ---------------- final 1-head attention over 32 tokens + fused output proj + ELU ----------------
__global__ void __launch_bounds__(256) final_attn(
    const float* __restrict__ q0, const float* __restrict__ Kf,
    const float* __restrict__ Vf, const float* __restrict__ Fmat,
    const float* __restrict__ fbias, float* __restrict__ out)
{
    __shared__ float sqv[Ee];
    __shared__ float sc[32];
    __shared__ float so[Ee];
    const int n = blockIdx.x;
    const int tid = threadIdx.x;
    const int warp = tid >> 5, lane = tid & 31;
    const float scale = 0.05590169943749474f;  // 1/sqrt(320)

    for (int e = tid; e < Ee; e += 256) sqv[e] = q0[(size_t)n*Ee + e];
    __syncthreads();

    #pragma unroll
    for (int i = 0; i < 4; i++) {
        int m = warp*4 + i;
        const float* kr = Kf + ((size_t)n*32 + m) * Ee;
        float s = 0.f;
        for (int e = lane; e < Ee; e += 32) s += sqv[e] * kr[e];
        #pragma unroll
        for (int o = 16; o > 0; o >>= 1) s += __shfl_down_sync(0xffffffffu, s, o);
        if (lane == 0) sc[m] = s * scale;
    }
    __syncthreads();

    if (warp == 0) {
        float v = sc[lane];
        float mx = v;
        #pragma unroll
        for (int o = 16; o > 0; o >>= 1) mx = fmaxf(mx, __shfl_xor_sync(0xffffffffu, mx, o));
        float ex = expf(v - mx);
        float sm = ex;
        #pragma unroll
        for (int o = 16; o > 0; o >>= 1) sm += __shfl_xor_sync(0xffffffffu, sm, o);
        sc[lane] = ex / sm;
    }
    __syncthreads();

    for (int e = tid; e < Ee; e += 256) {
        const float* vr = Vf + (size_t)n*32*Ee + e;
        float a = 0.f;
        #pragma unroll
        for (int m = 0; m < 32; m++) a += sc[m] * vr[(size_t)m*Ee];
        so[e] = a;
    }
    __syncthreads();

    #pragma unroll
    for (int i = 0; i < 4; i++) {
        int j = warp*4 + i;
        if (j < OUTD) {
            float s = 0.f;
            for (int e = lane; e < Ee; e += 32) s += so[e] * Fmat[(size_t)e*OUTD + j];
            #pragma unroll
            for (int o = 16; o > 0; o >>= 1) s += __shfl_down_sync(0xffffffffu, s, o);
            if (lane == 0) {
                float x = s + fbias[j];
                out[(size_t)n*OUTD + j] = x > 0.f ? x : expm1f(x);
            }
        }
    }
}

// ---------------- host ----------------
#define GETSYM(p, s) do { void* _t; cudaGetSymbolAddress(&_t, s); p = decltype(p)(_t); } while (0)

extern "C" void kernel_launch(void* const* d_in, const int* in_sizes, int n_in,
                              void* d_out, int out_size)
{
    const float* X        = (const float*)d_in[0];
    const int*   in_idx   = (const int*)  d_in[1];
    const int*   out_idx  = (const int*)  d_in[2];
    const float* in_Wq    = (const float*)d_in[3];
    const float* in_Wk    = (const float*)d_in[4];
    const float* in_Wv    = (const float*)d_in[5];
    const float* in_qkv_w = (const float*)d_in[6];
    const float* in_qkv_b = (const float*)d_in[7];
    const float* in_o_w   = (const float*)d_in[8];
    const float* in_o_b   = (const float*)d_in[9];
    const float* out_Wq   = (const float*)d_in[10];
    const float* out_Wk   = (const float*)d_in[11];
    const float* out_Wv   = (const float*)d_in[12];
    const float* out_qkv_w= (const float*)d_in[13];
    const float* out_qkv_b= (const float*)d_in[14];
    const float* out_o_w  = (const float*)d_in[15];
    const float* out_o_b  = (const float*)d_in[16];
    const float* fin_qkv_w= (const float*)d_in[17];
    const float* fin_qkv_b= (const float*)d_in[18];
    const float* fin_o_w  = (const float*)d_in[19];
    const float* fin_o_b  = (const float*)d_in[20];
    const float* Wfin     = (const float*)d_in[21];
    float* out = (float*)d_out;

    float *Mq_in, *Mk_in, *Mv_in, *Mq_out, *Mk_out, *Mv_out;
    float *Qmat, *Kmat_in, *Kmat_out, *Vmat_in, *Vmat_out;
    float *T_in_o, *T_out_o, *T_fin_o;
    float *qbias, *kbias_in, *kbias_out, *vbias_in, *vbias_out;
    float *Fmat, *fbias, *Q, *K, *V, *Oin, *Oout, *Kf, *Vf, *q0;
    int *rows_in, *rows_out, *rows_q0;
    GETSYM(Mq_in, g_Mq_in);   GETSYM(Mk_in, g_Mk_in);   GETSYM(Mv_in, g_Mv_in);
    GETSYM(Mq_out, g_Mq_out); GETSYM(Mk_out, g_Mk_out); GETSYM(Mv_out, g_Mv_out);
    GETSYM(Qmat, g_Qmat);     GETSYM(Kmat_in, g_Kmat_in); GETSYM(Kmat_out, g_Kmat_out);
    GETSYM(Vmat_in, g_Vmat_in); GETSYM(Vmat_out, g_Vmat_out);
    GETSYM(T_in_o, g_T_in_o); GETSYM(T_out_o, g_T_out_o); GETSYM(T_fin_o, g_T_fin_o);
    GETSYM(qbias, g_qbias);   GETSYM(kbias_in, g_kbias_in); GETSYM(kbias_out, g_kbias_out);
    GETSYM(vbias_in, g_vbias_in); GETSYM(vbias_out, g_vbias_out);
    GETSYM(Fmat, g_Fmat);     GETSYM(fbias, g_fbias);
    GETSYM(Q, g_Q); GETSYM(K, g_K); GETSYM(V, g_V);
    GETSYM(Oin, g_Oin); GETSYM(Oout, g_Oout);
    GETSYM(Kf, g_Kf); GETSYM(Vf, g_Vf); GETSYM(q0, g_q0);
    GETSYM(rows_in, g_rows_in); GETSYM(rows_out, g_rows_out); GETSYM(rows_q0, g_rows_q0);

    const int CB = 256;

    // 1) row gather tables + transposes of the three output-proj matrices
    build_rows<<<(Nn + CB - 1)/CB, CB>>>(in_idx, out_idx, rows_in, rows_out, rows_q0);
    dim3 tG(10, 10), tB(32, 8);
    transpose320<<<tG, tB>>>(in_o_w,  T_in_o);
    transpose320<<<tG, tB>>>(out_o_w, T_out_o);
    transpose320<<<tG, tB>>>(fin_o_w, T_fin_o);

    // 2) combined projection matrices: Mx = Wx @ wx.T  (coalesced warp-dot kernels)
    const int abTblocks = (Ee*Ee/4) / 8;   // 3200
    combine_abT_w<<<abTblocks, CB>>>(in_Wq,  in_qkv_w,             Mq_in);
    combine_abT_w<<<abTblocks, CB>>>(in_Wk,  in_qkv_w + Ee*Ee,     Mk_in);
    combine_abT_w<<<abTblocks, CB>>>(in_Wv,  in_qkv_w + 2*Ee*Ee,   Mv_in);
    combine_abT_w<<<abTblocks, CB>>>(out_Wq, out_qkv_w,            Mq_out);
    combine_abT_w<<<abTblocks, CB>>>(out_Wk, out_qkv_w + Ee*Ee,    Mk_out);
    combine_abT_w<<<abTblocks, CB>>>(out_Wv, out_qkv_w + 2*Ee*Ee,  Mv_out);

    // 3) fold layer output-proj into final q/k/v projections: Xmat = wo.T @ wxf.T = abT(woT, wxf)
    combine_abT_w<<<abTblocks, CB>>>(T_in_o,  fin_qkv_w,            Qmat);
    combine_abT_w<<<abTblocks, CB>>>(T_in_o,  fin_qkv_w + Ee*Ee,    Kmat_in);
    combine_abT_w<<<abTblocks, CB>>>(T_out_o, fin_qkv_w + Ee*Ee,    Kmat_out);
    combine_abT_w<<<abTblocks, CB>>>(T_in_o,  fin_qkv_w + 2*Ee*Ee,  Vmat_in);
    combine_abT_w<<<abTblocks, CB>>>(T_out_o, fin_qkv_w + 2*Ee*Ee,  Vmat_out);
    combine_bias_w<<<40, CB>>>(in_o_b,  fin_qkv_w,           fin_qkv_b,          qbias);
    combine_bias_w<<<40, CB>>>(in_o_b,  fin_qkv_w + Ee*Ee,   fin_qkv_b + Ee,     kbias_in);
    combine_bias_w<<<40, CB>>>(out_o_b, fin_qkv_w + Ee*Ee,   fin_qkv_b + Ee,     kbias_out);
    combine_bias_w<<<40, CB>>>(in_o_b,  fin_qkv_w + 2*Ee*Ee, fin_qkv_b + 2*Ee,   vbias_in);
    combine_bias_w<<<40, CB>>>(out_o_b, fin_qkv_w + 2*Ee*Ee, fin_qkv_b + 2*Ee,   vbias_out);

    // 4) fold final output-proj into readout: Fmat = wof.T @ W
    combine_fmat_w<<<(Ee*OUTD + 7)/8, CB>>>(T_fin_o, Wfin, Fmat);
    combine_fbias_w<<<1, CB>>>(fin_o_b, Wfin, fbias);

    const int Mfull = Nn * Ln;           // 160000 = 1250 * 128
    dim3 gemmGrid(Ee/64, Mfull/128);
    dim3 gemmGridQ0(Ee/64, (Nn + 63)/64);

    // 5) in-layer fused Q/K/V (tensor cores, one gathered-A pass), attention -> Oin
    gemm_tc<3><<<gemmGrid, 256>>>(X, rows_in,
        Mq_in, Mk_in, Mv_in,
        in_qkv_b, in_qkv_b + Ee, in_qkv_b + 2*Ee,
        Q, K, V, 16, 16, 0);
    attn16<<<Nn, 256>>>(Q, K, V, Oin);

    // 6) out-layer
    gemm_tc<3><<<gemmGrid, 256>>>(X, rows_out,
        Mq_out, Mk_out, Mv_out,
        out_qkv_b, out_qkv_b + Ee, out_qkv_b + 2*Ee,
        Q, K, V, 16, 16, 0);
    attn16<<<Nn, 256>>>(Q, K, V, Oout);

    // 7) final-layer K/V fused per source (interleaved halves: rows n*32+l, n*32+16+l)
    gemm_tc<2><<<gemmGrid, 256>>>(Oin, nullptr,
        Kmat_in, Vmat_in, nullptr,
        kbias_in, vbias_in, nullptr,
        Kf, Vf, nullptr, 16, 32, 0);
    gemm_tc<2><<<gemmGrid, 256>>>(Oout, nullptr,
        Kmat_out, Vmat_out, nullptr,
        kbias_out, vbias_out, nullptr,
        Kf, Vf, nullptr, 16, 32, 16);
    gemm320<<<gemmGridQ0, 256>>>(Oin, rows_q0, Nn, Qmat, qbias, q0);

    // 8) final attention + fused readout + ELU
    final_attn<<<Nn, 256>>>(q0, Kf, Vf, Fmat, fbias, out);
}

// round 7
// speedup vs baseline: 3.2098x; 1.1833x over previous
#include <cuda_runtime.h>
#include <math.h>
#include <stdint.h>

#define Nn 10000
#define Dn 15
#define Ln 16
#define Ee 320
#define OUTD 30
#define NH 5
#define HD 64

// ---------------- scratch (static device globals; no allocation) ----------------
__device__ float g_Mq_in[Ee*Ee], g_Mk_in[Ee*Ee], g_Mv_in[Ee*Ee];
__device__ float g_Mq_out[Ee*Ee], g_Mk_out[Ee*Ee], g_Mv_out[Ee*Ee];
__device__ float g_Qmat[Ee*Ee], g_Kmat_in[Ee*Ee], g_Kmat_out[Ee*Ee];
__device__ float g_Vmat_in[Ee*Ee], g_Vmat_out[Ee*Ee];
__device__ float g_T_in_o[Ee*Ee], g_T_out_o[Ee*Ee], g_T_fin_o[Ee*Ee];
__device__ float g_qbias[Ee], g_kbias_in[Ee], g_kbias_out[Ee], g_vbias_in[Ee], g_vbias_out[Ee];
__device__ float g_Fmat[Ee*OUTD], g_fbias[OUTD];
__device__ int   g_rows_in[Nn*Ln], g_rows_out[Nn*Ln], g_rows_q0[Nn];
__device__ float g_Q[(size_t)Nn*Ln*Ee], g_K[(size_t)Nn*Ln*Ee], g_V[(size_t)Nn*Ln*Ee];
__device__ float g_Oin[(size_t)Nn*Ln*Ee], g_Oout[(size_t)Nn*Ln*Ee];
__device__ float g_Kf[(size_t)Nn*2*Ln*Ee], g_Vf[(size_t)Nn*2*Ln*Ee];
__device__ float g_q0[(size_t)Nn*Ee];

// ---------------- helpers ----------------
__device__ __forceinline__ void mma_tf32(float* d, const uint32_t* a, uint32_t b0, uint32_t b1) {
    asm volatile(
        "mma.sync.aligned.m16n8k8.row.col.f32.tf32.tf32.f32 "
        "{%0,%1,%2,%3}, {%4,%5,%6,%7}, {%8,%9}, {%0,%1,%2,%3};"
        : "+f"(d[0]), "+f"(d[1]), "+f"(d[2]), "+f"(d[3])
        : "r"(a[0]), "r"(a[1]), "r"(a[2]), "r"(a[3]), "r"(b0), "r"(b1));
}

__device__ __forceinline__ void cp_async16(void* smem_dst, const void* gmem_src) {
    uint32_t d = (uint32_t)__cvta_generic_to_shared(smem_dst);
    asm volatile("cp.async.cg.shared.global [%0], [%1], 16;" :: "r"(d), "l"(gmem_src));
}
__device__ __forceinline__ void cp_commit() {
    asm volatile("cp.async.commit_group;" ::: "memory");
}

// ---------------- precompute kernels ----------------

// 320x320 transpose via smem tiles
__global__ void transpose320(const float* __restrict__ in, float* __restrict__ out) {
    __shared__ float tile[32][33];
    int bx = blockIdx.x * 32, by = blockIdx.y * 32;
    int x = bx + threadIdx.x;
    #pragma unroll
    for (int i = 0; i < 32; i += 8) {
        int y = by + threadIdx.y + i;
        tile[threadIdx.y + i][threadIdx.x] = in[(size_t)y*Ee + x];
    }
    __syncthreads();
    x = by + threadIdx.x;
    #pragma unroll
    for (int i = 0; i < 32; i += 8) {
        int y = bx + threadIdx.y + i;
        out[(size_t)y*Ee + x] = tile[threadIdx.x][threadIdx.y + i];
    }
}

// Batched tiled C = A @ B^T (all 320x320): one launch, grid.z selects task
#define NCOMB 11
struct CombineBatch {
    const float* A[NCOMB];
    const float* B[NCOMB];
    float*       C[NCOMB];
};
__global__ void __launch_bounds__(256) combine_batch(CombineBatch p) {
    const float* __restrict__ A = p.A[blockIdx.z];
    const float* __restrict__ B = p.B[blockIdx.z];
    float* __restrict__ C = p.C[blockIdx.z];
    constexpr int BK = 16;
    __shared__ float As[BK][64];
    __shared__ float Bs[BK][64];
    const int tid = threadIdx.x;
    const int bm = blockIdx.y * 64;
    const int bn = blockIdx.x * 64;
    const int tcol = tid & 15, trow = tid >> 4;
    const int aRow = tid >> 2, aCol = (tid & 3) << 2;

    float acc[4][4];
    #pragma unroll
    for (int i = 0; i < 4; i++)
        #pragma unroll
        for (int j = 0; j < 4; j++) acc[i][j] = 0.f;

    for (int k0 = 0; k0 < Ee; k0 += BK) {
        float4 a4 = *(const float4*)(A + (size_t)(bm + aRow)*Ee + k0 + aCol);
        float4 b4 = *(const float4*)(B + (size_t)(bn + aRow)*Ee + k0 + aCol);
        As[aCol+0][aRow] = a4.x; As[aCol+1][aRow] = a4.y;
        As[aCol+2][aRow] = a4.z; As[aCol+3][aRow] = a4.w;
        Bs[aCol+0][aRow] = b4.x; Bs[aCol+1][aRow] = b4.y;
        Bs[aCol+2][aRow] = b4.z; Bs[aCol+3][aRow] = b4.w;
        __syncthreads();
        #pragma unroll
        for (int kk = 0; kk < BK; kk++) {
            float ar[4], br[4];
            #pragma unroll
            for (int i = 0; i < 4; i++) ar[i] = As[kk][trow*4 + i];
            #pragma unroll
            for (int j = 0; j < 4; j++) br[j] = Bs[kk][tcol*4 + j];
            #pragma unroll
            for (int i = 0; i < 4; i++)
                #pragma unroll
                for (int j = 0; j < 4; j++)
                    acc[i][j] += ar[i] * br[j];
        }
        __syncthreads();
    }
    #pragma unroll
    for (int i = 0; i < 4; i++)
        #pragma unroll
        for (int j = 0; j < 4; j++)
            C[(size_t)(bm + trow*4 + i)*Ee + bn + tcol*4 + j] = acc[i][j];
}

// Batched bias combine: out[j] = sum_e bo[e]*Bq[j*E+e] + b2[j]; grid=(40, 5)
#define NBIAS 5
struct BiasBatch {
    const float* bo[NBIAS];
    const float* Bq[NBIAS];
    const float* b2[NBIAS];
    float*       out[NBIAS];
};
__global__ void __launch_bounds__(256) bias_batch(BiasBatch p) {
    int task = blockIdx.y;
    const float* __restrict__ bo = p.bo[task];
    const float* __restrict__ Bq = p.Bq[task];
    int j = (blockIdx.x * 256 + threadIdx.x) >> 5;
    int lane = threadIdx.x & 31;
    if (j >= Ee) return;
    const float* br = Bq + (size_t)j*Ee;
    float s = 0.f;
    #pragma unroll
    for (int e = lane, i = 0; i < Ee/32; e += 32, i++) s += bo[e] * br[e];
    #pragma unroll
    for (int off = 16; off > 0; off >>= 1) s += __shfl_down_sync(0xffffffffu, s, off);
    if (lane == 0) p.out[task][j] = s + p.b2[task][j];
}

// warp-per-output: Fmat[e*OUTD+j] = sum_t fowT[e*E+t]*W[t*OUTD+j]
__global__ void combine_fmat_w(const float* __restrict__ fowT, const float* __restrict__ W,
                               float* __restrict__ out) {
    int o = (blockIdx.x * 256 + threadIdx.x) >> 5;
    int lane = threadIdx.x & 31;
    if (o >= Ee*OUTD) return;
    int e = o / OUTD, j = o % OUTD;
    const float* fr = fowT + (size_t)e*Ee;
    float s = 0.f;
    #pragma unroll
    for (int t = lane, i = 0; i < Ee/32; t += 32, i++) s += fr[t] * W[(size_t)t*OUTD + j];
    #pragma unroll
    for (int off = 16; off > 0; off >>= 1) s += __shfl_down_sync(0xffffffffu, s, off);
    if (lane == 0) out[o] = s;
}

__global__ void combine_fbias_w(const float* __restrict__ fob, const float* __restrict__ W,
                                float* __restrict__ out) {
    int warp = threadIdx.x >> 5, lane = threadIdx.x & 31;
    for (int j = warp; j < OUTD; j += 8) {
        float s = 0.f;
        #pragma unroll
        for (int t = lane, i = 0; i < Ee/32; t += 32, i++) s += fob[t] * W[(size_t)t*OUTD + j];
        #pragma unroll
        for (int off = 16; off > 0; off >>= 1) s += __shfl_down_sync(0xffffffffu, s, off);
        if (lane == 0) out[j] = s;
    }
}

__global__ void build_rows(const int* __restrict__ in_idx, const int* __restrict__ out_idx,
                           int* __restrict__ rin, int* __restrict__ rout, int* __restrict__ rq0) {
    int n = blockIdx.x * blockDim.x + threadIdx.x;
    if (n >= Nn) return;
    rin[n*Ln] = n;
    rout[n*Ln] = n;
    rq0[n] = n*Ln;
    #pragma unroll
    for (int d = 0; d < Dn; d++) {
        rin[n*Ln + 1 + d]  = in_idx[n*Dn + d];
        rout[n*Ln + 1 + d] = out_idx[n*Dn + d];
    }
}

// ---------------- tensor-core multi-B GEMM, cp.async double-buffered ----------------
// tf32 HMMA (fp32 bits fed directly; HW truncates), fp32 accumulate.
// BM=128, BN=64, BK=32, 2 stages in dynamic smem. Requires M % 128 == 0.
template<int NMAT>
__global__ void __launch_bounds__(256) gemm_tc(
    const float* __restrict__ A, const int* __restrict__ rows,
    const float* __restrict__ B0, const float* __restrict__ B1, const float* __restrict__ B2,
    const float* __restrict__ bias0, const float* __restrict__ bias1, const float* __restrict__ bias2,
    float* __restrict__ C0, float* __restrict__ C1, float* __restrict__ C2,
    int out_grp, int out_str, int out_off)
{
    constexpr int BM = 128, BN = 64, BK = 32;
    constexpr int ASTR = 36;   // conflict-free A frag loads
    constexpr int BSTR = 72;   // conflict-free B frag loads
    constexpr int NT = Ee / BK;  // 10
    extern __shared__ float smp[];
    float* AsBase = smp;                      // [2][BM*ASTR]
    float* BsBase = smp + 2*BM*ASTR;          // [2][NMAT][BK*BSTR]

    const int tid = threadIdx.x;
    const int bm = blockIdx.y * BM;
    const int bn = blockIdx.x * BN;
    const int warpId = tid >> 5, lane = tid & 31;
    const int wm = (warpId & 3) * 32;
    const int wn = (warpId >> 2) * 32;
    const int g = lane >> 2, t = lane & 3;

    const float* Bp[NMAT]; const float* biasp[NMAT]; float* Cp[NMAT];
    Bp[0] = B0; biasp[0] = bias0; Cp[0] = C0;
    if (NMAT > 1) { Bp[1] = B1; biasp[1] = bias1; Cp[1] = C1; }
    if (NMAT > 2) { Bp[2] = B2; biasp[2] = bias2; Cp[2] = C2; }

    float acc[NMAT][2][4][4];
    #pragma unroll
    for (int q = 0; q < NMAT; q++)
        #pragma unroll
        for (int mi = 0; mi < 2; mi++)
            #pragma unroll
            for (int ni = 0; ni < 4; ni++)
                #pragma unroll
                for (int v = 0; v < 4; v++) acc[q][mi][ni][v] = 0.f;

    // A loader: 4 rows/thread (rows aRow + 32i), 16B each
    const int aRow = tid >> 3;
    const int aCol = (tid & 7) * 4;
    size_t gA[4];
    #pragma unroll
    for (int i = 0; i < 4; i++) {
        int m = bm + aRow + i*32;
        gA[i] = (size_t)(rows ? rows[m] : m) * Ee;
    }
    // B loader: 2 rows/thread/matrix
    const int bRow = tid >> 4;
    const int bCol = (tid & 15) * 4;

    auto issue = [&](int kt, int st) {
        float* As = AsBase + st*BM*ASTR;
        #pragma unroll
        for (int i = 0; i < 4; i++)
            cp_async16(&As[(aRow + i*32)*ASTR + aCol], A + gA[i] + kt*BK + aCol);
        #pragma unroll
        for (int q = 0; q < NMAT; q++) {
            float* Bs = BsBase + (st*NMAT + q)*BK*BSTR;
            #pragma unroll
            for (int i = 0; i < 2; i++) {
                int kr = bRow + i*16;
                cp_async16(&Bs[kr*BSTR + bCol], Bp[q] + (size_t)(kt*BK + kr)*Ee + bn + bCol);
            }
        }
    };

    auto compute = [&](int st) {
        const float* As = AsBase + st*BM*ASTR;
        #pragma unroll
        for (int kk = 0; kk < BK; kk += 8) {
            uint32_t afr[2][4];
            #pragma unroll
            for (int mi = 0; mi < 2; mi++) {
                int r0 = wm + mi*16 + g;
                afr[mi][0] = __float_as_uint(As[(r0    )*ASTR + kk + t    ]);
                afr[mi][1] = __float_as_uint(As[(r0 + 8)*ASTR + kk + t    ]);
                afr[mi][2] = __float_as_uint(As[(r0    )*ASTR + kk + t + 4]);
                afr[mi][3] = __float_as_uint(As[(r0 + 8)*ASTR + kk + t + 4]);
            }
            #pragma unroll
            for (int q = 0; q < NMAT; q++) {
                const float* Bs = BsBase + (st*NMAT + q)*BK*BSTR;
                #pragma unroll
                for (int ni = 0; ni < 4; ni++) {
                    int nc = wn + ni*8 + g;
                    uint32_t b0 = __float_as_uint(Bs[(kk + t    )*BSTR + nc]);
                    uint32_t b1 = __float_as_uint(Bs[(kk + t + 4)*BSTR + nc]);
                    #pragma unroll
                    for (int mi = 0; mi < 2; mi++)
                        mma_tf32(acc[q][mi][ni], afr[mi], b0, b1);
                }
            }
        }
    };

    // pipeline: prefetch tile 0, then steady-state double buffer
    issue(0, 0);
    cp_commit();

    #pragma unroll 1
    for (int kt = 0; kt < NT; kt++) {
        int st = kt & 1;
        if (kt + 1 < NT) {
            issue(kt + 1, st ^ 1);
            cp_commit();
            asm volatile("cp.async.wait_group 1;" ::: "memory");
        } else {
            asm volatile("cp.async.wait_group 0;" ::: "memory");
        }
        __syncthreads();
        compute(st);
        __syncthreads();
    }

    // epilogue
    #pragma unroll
    for (int q = 0; q < NMAT; q++) {
        #pragma unroll
        for (int ni = 0; ni < 4; ni++) {
            int n = bn + wn + ni*8 + 2*t;
            float bb0 = biasp[q][n], bb1 = biasp[q][n+1];
            #pragma unroll
            for (int mi = 0; mi < 2; mi++) {
                int m0 = bm + wm + mi*16 + g;
                int m1 = m0 + 8;
                int cr0 = (m0 / out_grp) * out_str + (m0 % out_grp) + out_off;
                int cr1 = (m1 / out_grp) * out_str + (m1 % out_grp) + out_off;
                float2 v0, v1;
                v0.x = acc[q][mi][ni][0] + bb0; v0.y = acc[q][mi][ni][1] + bb1;
                v1.x = acc[q][mi][ni][2] + bb0; v1.y = acc[q][mi][ni][3] + bb1;
                *(float2*)(Cp[q] + (size_t)cr0*Ee + n) = v0;
                *(float2*)(Cp[q] + (size_t)cr1*Ee + n) = v1;
            }
        }
    }
}

// ---------------- single-B SIMT GEMM with M guard (q0: M = 10000, fp32 exact) ----------------
__global__ void __launch_bounds__(256) gemm320(
    const float* __restrict__ A, const int* __restrict__ rows, int M,
    const float* __restrict__ B, const float* __restrict__ bias,
    float* __restrict__ C)
{
    constexpr int BM = 64, BN = 64, BK = 16;
    __shared__ float As[BK][BM];
    __shared__ float Bs[BK][BN];
    const int tid = threadIdx.x;
    const int bm = blockIdx.y * BM;
    const int bn = blockIdx.x * BN;
    const int tcol = tid & 15;
    const int trow = tid >> 4;

    float acc[4][4];
    #pragma unroll
    for (int i = 0; i < 4; i++)
        #pragma unroll
        for (int j = 0; j < 4; j++) acc[i][j] = 0.f;

    const int aRow = tid >> 2;
    const int aCol = (tid & 3) << 2;
    int r = bm + aRow; if (r >= M) r = M - 1;
    const size_t ga = (size_t)(rows ? rows[r] : r) * Ee;
    const int bRow = tid >> 4;
    const int bCol = (tid & 15) << 2;

    for (int k0 = 0; k0 < Ee; k0 += BK) {
        float4 a4 = *(const float4*)(A + ga + k0 + aCol);
        float4 b4 = *(const float4*)(B + (size_t)(k0 + bRow)*Ee + bn + bCol);
        As[aCol+0][aRow] = a4.x; As[aCol+1][aRow] = a4.y;
        As[aCol+2][aRow] = a4.z; As[aCol+3][aRow] = a4.w;
        *(float4*)&Bs[bRow][bCol] = b4;
        __syncthreads();

        #pragma unroll
        for (int kk = 0; kk < BK; kk++) {
            float ar[4], br[4];
            #pragma unroll
            for (int i = 0; i < 4; i++) ar[i] = As[kk][trow*4 + i];
            #pragma unroll
            for (int j = 0; j < 4; j++) br[j] = Bs[kk][tcol*4 + j];
            #pragma unroll
            for (int i = 0; i < 4; i++)
                #pragma unroll
                for (int j = 0; j < 4; j++)
                    acc[i][j] += ar[i] * br[j];
        }
        __syncthreads();
    }

    float bb[4];
    #pragma unroll
    for (int j = 0; j < 4; j++) bb[j] = bias[bn + tcol*4 + j];
    #pragma unroll
    for (int i = 0; i < 4; i++) {
        int m = bm + trow*4 + i;
        if (m < M) {
            float4 o;
            o.x = acc[i][0] + bb[0];
            o.y = acc[i][1] + bb[1];
            o.z = acc[i][2] + bb[2];
            o.w = acc[i][3] + bb[3];
            *(float4*)(C + (size_t)m*Ee + bn + tcol*4) = o;
        }
    }
}

// ---------------- per-node 5-head L=16 attention (writes pre-output-proj O) ----------------
__global__ void __launch_bounds__(256) attn16(
    const float* __restrict__ Q, const float* __restrict__ K,
    const float* __restrict__ V, float* __restrict__ O)
{
    constexpr int LP = 68;
    __shared__ float sq[Ln][LP], sk[Ln][LP], sv[Ln][LP];
    __shared__ float ss[Ln][Ln + 1];
    const int n = blockIdx.x;
    const int tid = threadIdx.x;
    const size_t base = (size_t)n * Ln * Ee;

    const int ll = tid >> 4;          // 0..15
    const int lc = (tid & 15) << 2;   // 0..60

    for (int h = 0; h < NH; h++) {
        const int hc = h * HD;
        float4 q4 = *(const float4*)(Q + base + (size_t)ll*Ee + hc + lc);
        float4 k4 = *(const float4*)(K + base + (size_t)ll*Ee + hc + lc);
        float4 v4 = *(const float4*)(V + base + (size_t)ll*Ee + hc + lc);
        sq[ll][lc+0]=q4.x; sq[ll][lc+1]=q4.y; sq[ll][lc+2]=q4.z; sq[ll][lc+3]=q4.w;
        sk[ll][lc+0]=k4.x; sk[ll][lc+1]=k4.y; sk[ll][lc+2]=k4.z; sk[ll][lc+3]=k4.w;
        sv[ll][lc+0]=v4.x; sv[ll][lc+1]=v4.y; sv[ll][lc+2]=v4.z; sv[ll][lc+3]=v4.w;
        __syncthreads();

        {
            const int sl = tid >> 4, sm = tid & 15;
            float s = 0.f;
            #pragma unroll
            for (int c = 0; c < HD; c++) s += sq[sl][c] * sk[sm][c];
            ss[sl][sm] = s * 0.125f;  // 1/sqrt(64)
        }
        __syncthreads();

        if (tid < Ln) {
            float mx = -1e30f;
            #pragma unroll
            for (int m = 0; m < Ln; m++) mx = fmaxf(mx, ss[tid][m]);
            float sum = 0.f;
            #pragma unroll
            for (int m = 0; m < Ln; m++) { float e = expf(ss[tid][m] - mx); ss[tid][m] = e; sum += e; }
            float inv = 1.f / sum;
            #pragma unroll
            for (int m = 0; m < Ln; m++) ss[tid][m] *= inv;
        }
        __syncthreads();

        #pragma unroll
        for (int i = 0; i < 4; i++) {
            int idx = tid + i * 256;
            int ol = idx >> 6, oc = idx & 63;
            float a = 0.f;
            #pragma unroll
            for (int m = 0; m < Ln; m++) a += ss[ol][m] * sv[m][oc];
            O[base + (size_t)ol*Ee + hc + oc] = a;
        }
        __syncthreads();
    }
}

// ---------------- final 1-head attention over 32 tokens + fused output proj + ELU ----------------
__global__ void __launch_bounds__(256) final_attn(
    const float* __restrict__ q0, const float* __restrict__ Kf,
    const float* __restrict__ Vf, const float* __restrict__ Fmat,
    const float* __restrict__ fbias, float* __restrict__ out)
{
    __shared__ float sqv[Ee];
    __shared__ float sc[32];
    __shared__ float so[Ee];
    const int n = blockIdx.x;
    const int tid = threadIdx.x;
    const int warp = tid >> 5, lane = tid & 31;
    const float scale = 0.05590169943749474f;  // 1/sqrt(320)

    for (int e = tid; e < Ee; e += 256) sqv[e] = q0[(size_t)n*Ee + e];
    __syncthreads();

    #pragma unroll
    for (int i = 0; i < 4; i++) {
        int m = warp*4 + i;
        const float* kr = Kf + ((size_t)n*32 + m) * Ee;
        float s = 0.f;
        for (int e = lane; e < Ee; e += 32) s += sqv[e] * kr[e];
        #pragma unroll
        for (int o = 16; o > 0; o >>= 1) s += __shfl_down_sync(0xffffffffu, s, o);
        if (lane == 0) sc[m] = s * scale;
    }
    __syncthreads();

    if (warp == 0) {
        float v = sc[lane];
        float mx = v;
        #pragma unroll
        for (int o = 16; o > 0; o >>= 1) mx = fmaxf(mx, __shfl_xor_sync(0xffffffffu, mx, o));
        float ex = expf(v - mx);
        float sm = ex;
        #pragma unroll
        for (int o = 16; o > 0; o >>= 1) sm += __shfl_xor_sync(0xffffffffu, sm, o);
        sc[lane] = ex / sm;
    }
    __syncthreads();

    for (int e = tid; e < Ee; e += 256) {
        const float* vr = Vf + (size_t)n*32*Ee + e;
        float a = 0.f;
        #pragma unroll
        for (int m = 0; m < 32; m++) a += sc[m] * vr[(size_t)m*Ee];
        so[e] = a;
    }
    __syncthreads();

    #pragma unroll
    for (int i = 0; i < 4; i++) {
        int j = warp*4 + i;
        if (j < OUTD) {
            float s = 0.f;
            for (int e = lane; e < Ee; e += 32) s += so[e] * Fmat[(size_t)e*OUTD + j];
            #pragma unroll
            for (int o = 16; o > 0; o >>= 1) s += __shfl_down_sync(0xffffffffu, s, o);
            if (lane == 0) {
                float x = s + fbias[j];
                out[(size_t)n*OUTD + j] = x > 0.f ? x : expm1f(x);
            }
        }
    }
}

// ---------------- host ----------------
#define GETSYM(p, s) do { void* _t; cudaGetSymbolAddress(&_t, s); p = decltype(p)(_t); } while (0)

extern "C" void kernel_launch(void* const* d_in, const int* in_sizes, int n_in,
                              void* d_out, int out_size)
{
    const float* X        = (const float*)d_in[0];
    const int*   in_idx   = (const int*)  d_in[1];
    const int*   out_idx  = (const int*)  d_in[2];
    const float* in_Wq    = (const float*)d_in[3];
    const float* in_Wk    = (const float*)d_in[4];
    const float* in_Wv    = (const float*)d_in[5];
    const float* in_qkv_w = (const float*)d_in[6];
    const float* in_qkv_b = (const float*)d_in[7];
    const float* in_o_w   = (const float*)d_in[8];
    const float* in_o_b   = (const float*)d_in[9];
    const float* out_Wq   = (const float*)d_in[10];
    const float* out_Wk   = (const float*)d_in[11];
    const float* out_Wv   = (const float*)d_in[12];
    const float* out_qkv_w= (const float*)d_in[13];
    const float* out_qkv_b= (const float*)d_in[14];
    const float* out_o_w  = (const float*)d_in[15];
    const float* out_o_b  = (const float*)d_in[16];
    const float* fin_qkv_w= (const float*)d_in[17];
    const float* fin_qkv_b= (const float*)d_in[18];
    const float* fin_o_w  = (const float*)d_in[19];
    const float* fin_o_b  = (const float*)d_in[20];
    const float* Wfin     = (const float*)d_in[21];
    float* out = (float*)d_out;

    float *Mq_in, *Mk_in, *Mv_in, *Mq_out, *Mk_out, *Mv_out;
    float *Qmat, *Kmat_in, *Kmat_out, *Vmat_in, *Vmat_out;
    float *T_in_o, *T_out_o, *T_fin_o;
    float *qbias, *kbias_in, *kbias_out, *vbias_in, *vbias_out;
    float *Fmat, *fbias, *Q, *K, *V, *Oin, *Oout, *Kf, *Vf, *q0;
    int *rows_in, *rows_out, *rows_q0;
    GETSYM(Mq_in, g_Mq_in);   GETSYM(Mk_in, g_Mk_in);   GETSYM(Mv_in, g_Mv_in);
    GETSYM(Mq_out, g_Mq_out); GETSYM(Mk_out, g_Mk_out); GETSYM(Mv_out, g_Mv_out);
    GETSYM(Qmat, g_Qmat);     GETSYM(Kmat_in, g_Kmat_in); GETSYM(Kmat_out, g_Kmat_out);
    GETSYM(Vmat_in, g_Vmat_in); GETSYM(Vmat_out, g_Vmat_out);
    GETSYM(T_in_o, g_T_in_o); GETSYM(T_out_o, g_T_out_o); GETSYM(T_fin_o, g_T_fin_o);
    GETSYM(qbias, g_qbias);   GETSYM(kbias_in, g_kbias_in); GETSYM(kbias_out, g_kbias_out);
    GETSYM(vbias_in, g_vbias_in); GETSYM(vbias_out, g_vbias_out);
    GETSYM(Fmat, g_Fmat);     GETSYM(fbias, g_fbias);
    GETSYM(Q, g_Q); GETSYM(K, g_K); GETSYM(V, g_V);
    GETSYM(Oin, g_Oin); GETSYM(Oout, g_Oout);
    GETSYM(Kf, g_Kf); GETSYM(Vf, g_Vf); GETSYM(q0, g_q0);
    GETSYM(rows_in, g_rows_in); GETSYM(rows_out, g_rows_out); GETSYM(rows_q0, g_rows_q0);

    const int CB = 256;

    // dynamic smem opt-in for the pipelined GEMMs (idempotent host-side call)
    const int SMEM3 = (2*128*36 + 2*3*32*72) * 4;   // 92160
    const int SMEM2 = (2*128*36 + 2*2*32*72) * 4;   // 73728
    cudaFuncSetAttribute(gemm_tc<3>, cudaFuncAttributeMaxDynamicSharedMemorySize, SMEM3);
    cudaFuncSetAttribute(gemm_tc<2>, cudaFuncAttributeMaxDynamicSharedMemorySize, SMEM2);

    // 1) row gather tables + transposes of the three output-proj matrices
    build_rows<<<(Nn + CB - 1)/CB, CB>>>(in_idx, out_idx, rows_in, rows_out, rows_q0);
    dim3 tG(10, 10), tB(32, 8);
    transpose320<<<tG, tB>>>(in_o_w,  T_in_o);
    transpose320<<<tG, tB>>>(out_o_w, T_out_o);
    transpose320<<<tG, tB>>>(fin_o_w, T_fin_o);

    // 2+3) all 11 combined matrices in ONE batched launch: C = A @ B^T
    CombineBatch cb;
    cb.A[0] = in_Wq;   cb.B[0] = in_qkv_w;            cb.C[0] = Mq_in;
    cb.A[1] = in_Wk;   cb.B[1] = in_qkv_w + Ee*Ee;    cb.C[1] = Mk_in;
    cb.A[2] = in_Wv;   cb.B[2] = in_qkv_w + 2*Ee*Ee;  cb.C[2] = Mv_in;
    cb.A[3] = out_Wq;  cb.B[3] = out_qkv_w;           cb.C[3] = Mq_out;
    cb.A[4] = out_Wk;  cb.B[4] = out_qkv_w + Ee*Ee;   cb.C[4] = Mk_out;
    cb.A[5] = out_Wv;  cb.B[5] = out_qkv_w + 2*Ee*Ee; cb.C[5] = Mv_out;
    cb.A[6] = T_in_o;  cb.B[6] = fin_qkv_w;           cb.C[6] = Qmat;
    cb.A[7] = T_in_o;  cb.B[7] = fin_qkv_w + Ee*Ee;   cb.C[7] = Kmat_in;
    cb.A[8] = T_out_o; cb.B[8] = fin_qkv_w + Ee*Ee;   cb.C[8] = Kmat_out;
    cb.A[9] = T_in_o;  cb.B[9] = fin_qkv_w + 2*Ee*Ee; cb.C[9] = Vmat_in;
    cb.A[10]= T_out_o; cb.B[10]= fin_qkv_w + 2*Ee*Ee; cb.C[10]= Vmat_out;
    combine_batch<<<dim3(5, 5, NCOMB), CB>>>(cb);

    BiasBatch bb;
    bb.bo[0] = in_o_b;  bb.Bq[0] = fin_qkv_w;           bb.b2[0] = fin_qkv_b;          bb.out[0] = qbias;
    bb.bo[1] = in_o_b;  bb.Bq[1] = fin_qkv_w + Ee*Ee;   bb.b2[1] = fin_qkv_b + Ee;     bb.out[1] = kbias_in;
    bb.bo[2] = out_o_b; bb.Bq[2] = fin_qkv_w + Ee*Ee;   bb.b2[2] = fin_qkv_b + Ee;     bb.out[2] = kbias_out;
    bb.bo[3] = in_o_b;  bb.Bq[3] = fin_qkv_w + 2*Ee*Ee; bb.b2[3] = fin_qkv_b + 2*Ee;   bb.out[3] = vbias_in;
    bb.bo[4] = out_o_b; bb.Bq[4] = fin_qkv_w + 2*Ee*Ee; bb.b2[4] = fin_qkv_b + 2*Ee;   bb.out[4] = vbias_out;
    bias_batch<<<dim3(40, NBIAS), CB>>>(bb);

    // 4) fold final output-proj into readout: Fmat = wof.T @ W
    combine_fmat_w<<<(Ee*OUTD + 7)/8, CB>>>(T_fin_o, Wfin, Fmat);
    combine_fbias_w<<<1, CB>>>(fin_o_b, Wfin, fbias);

    const int Mfull = Nn * Ln;           // 160000 = 1250 * 128
    dim3 gemmGrid(Ee/64, Mfull/128);
    dim3 gemmGridQ0(Ee/64, (Nn + 63)/64);

    // 5) in-layer fused Q/K/V (tensor cores, one gathered-A pass), attention -> Oin
    gemm_tc<3><<<gemmGrid, 256, SMEM3>>>(X, rows_in,
        Mq_in, Mk_in, Mv_in,
        in_qkv_b, in_qkv_b + Ee, in_qkv_b + 2*Ee,
        Q, K, V, 16, 16, 0);
    attn16<<<Nn, 256>>>(Q, K, V, Oin);

    // 6) out-layer
    gemm_tc<3><<<gemmGrid, 256, SMEM3>>>(X, rows_out,
        Mq_out, Mk_out, Mv_out,
        out_qkv_b, out_qkv_b + Ee, out_qkv_b + 2*Ee,
        Q, K, V, 16, 16, 0);
    attn16<<<Nn, 256>>>(Q, K, V, Oout);

    // 7) final-layer K/V fused per source (interleaved halves: rows n*32+l, n*32+16+l)
    gemm_tc<2><<<gemmGrid, 256, SMEM2>>>(Oin, nullptr,
        Kmat_in, Vmat_in, nullptr,
        kbias_in, vbias_in, nullptr,
        Kf, Vf, nullptr, 16, 32, 0);
    gemm_tc<2><<<gemmGrid, 256, SMEM2>>>(Oout, nullptr,
        Kmat_out, Vmat_out, nullptr,
        kbias_out, vbias_out, nullptr,
        Kf, Vf, nullptr, 16, 32, 16);
    gemm320<<<gemmGridQ0, 256>>>(Oin, rows_q0, Nn, Qmat, qbias, q0);

    // 8) final attention + fused readout + ELU
    final_attn<<<Nn, 256>>>(q0, Kf, Vf, Fmat, fbias, out);
}